// round 1
// baseline (speedup 1.0000x reference)
#include <cuda_runtime.h>

// Problem constants
#define B_  256
#define S_  2048
#define I_  128
#define J_  40    // LSTM_IN
#define G_  80    // 4*H
#define H_  20

// Scratch: gx[s][b][g]  (S*B*80 floats = 167.8 MB) — device global, allocation-free.
__device__ float g_gx[(size_t)S_ * B_ * G_];

// ---------------- f32x2 packed helpers (sm_103a) ----------------
__device__ __forceinline__ unsigned long long pk2(float lo, float hi) {
    unsigned long long r;
    asm("mov.b64 %0, {%1, %2};" : "=l"(r) : "f"(lo), "f"(hi));
    return r;
}
__device__ __forceinline__ void upk2(unsigned long long v, float& lo, float& hi) {
    asm("mov.b64 {%0, %1}, %2;" : "=f"(lo), "=f"(hi) : "l"(v));
}
__device__ __forceinline__ void fma2(unsigned long long& d, unsigned long long a,
                                     unsigned long long b) {
    asm("fma.rn.f32x2 %0, %1, %2, %0;" : "+l"(d) : "l"(a), "l"(b));
}

__device__ __forceinline__ float sigmoid_f(float x) {
    // exp(-x) underflows/overflows gracefully (0 or inf) -> sigmoid -> 1 or 0. Safe.
    float e = __expf(-x);
    return __fdividef(1.f, 1.f + e);
}
__device__ __forceinline__ float tanh_f(float x) {
    // clamp to avoid inf/inf = NaN for very negative args
    x = fminf(fmaxf(x, -15.f), 15.f);
    float e = __expf(-2.f * x);
    return __fdividef(1.f - e, 1.f + e);
}

// ---------------- GEMM kernel: gx = relu(feed@W1^T + b1) @ Wih^T + (bih+bhh) ----------------
// Tile: 128 rows (= fixed s, 128 consecutive b) per block, 256 threads.
// Thread tile phase1: 4 rows x 5 cols (j). Phase2: 4 rows x 10 cols (g).
// k-paired f32x2 accumulation: even-k partials in .lo, odd-k in .hi.

#define TILE_R 128

struct SmemG {
    float feed[TILE_R][I_ + 4];  // stride 132 (16B-aligned rows, 2-way worst conflict)
    float x[TILE_R][J_ + 4];     // stride 44
    float w1[J_][I_ + 4];        // stride 132
    float wih[G_][J_ + 2];       // stride 42 (conflict-free for g = cg*10+p pattern)
    float b1v[J_];
    float b2v[G_];
};

__global__ __launch_bounds__(256, 1) void gemm_kernel(
    const float* __restrict__ feed, const float* __restrict__ W1,
    const float* __restrict__ b1, const float* __restrict__ Wih,
    const float* __restrict__ bih, const float* __restrict__ bhh)
{
    extern __shared__ char smem_raw[];
    SmemG& sm = *reinterpret_cast<SmemG*>(smem_raw);
    const int tid  = threadIdx.x;
    const int tile = blockIdx.x;           // 4096 tiles
    const int s    = tile >> 1;            // 2 tiles per timestep
    const int bb   = (tile & 1) * 128;     // batch base

    // --- stage weights/biases ---
    for (int idx = tid; idx < J_ * I_; idx += 256)
        sm.w1[idx / I_][idx % I_] = W1[idx];
    for (int idx = tid; idx < G_ * J_; idx += 256)
        sm.wih[idx / J_][idx % J_] = Wih[idx];
    if (tid < J_) sm.b1v[tid] = b1[tid];
    if (tid < G_) sm.b2v[tid] = bih[tid] + bhh[tid];

    // --- stage feed tile: 128 rows x 128 f32, float4, coalesced per warp ---
    for (int idx = tid; idx < TILE_R * (I_ / 4); idx += 256) {
        int r  = idx >> 5;       // row 0..127
        int c4 = idx & 31;       // float4 index 0..31
        float4 v = *reinterpret_cast<const float4*>(
            feed + ((size_t)(bb + r) * S_ + s) * I_ + c4 * 4);
        *reinterpret_cast<float4*>(&sm.feed[r][c4 * 4]) = v;
    }
    __syncthreads();

    const int cg = tid & 7;   // 8 col groups
    const int rg = tid >> 3;  // 32 row groups
    const int r0 = rg * 4;

    // --- phase 1: x[r][j], j0 = cg*5, 5 cols ---
    {
        const int j0 = cg * 5;
        unsigned long long acc[4][5];
#pragma unroll
        for (int q = 0; q < 4; q++)
#pragma unroll
            for (int p = 0; p < 5; p++) acc[q][p] = 0ull;

#pragma unroll 4
        for (int kp = 0; kp < I_ / 2; kp++) {
            const int k = kp * 2;
            unsigned long long fr[4], wj[5];
#pragma unroll
            for (int q = 0; q < 4; q++)
                fr[q] = *reinterpret_cast<const unsigned long long*>(&sm.feed[r0 + q][k]);
#pragma unroll
            for (int p = 0; p < 5; p++)
                wj[p] = *reinterpret_cast<const unsigned long long*>(&sm.w1[j0 + p][k]);
#pragma unroll
            for (int q = 0; q < 4; q++)
#pragma unroll
                for (int p = 0; p < 5; p++) fma2(acc[q][p], fr[q], wj[p]);
        }
#pragma unroll
        for (int q = 0; q < 4; q++)
#pragma unroll
            for (int p = 0; p < 5; p++) {
                float lo, hi;
                upk2(acc[q][p], lo, hi);
                float v = lo + hi + sm.b1v[j0 + p];
                sm.x[r0 + q][j0 + p] = fmaxf(v, 0.f);
            }
    }
    __syncthreads();

    // --- phase 2: gx[r][g], g0 = cg*10, 10 cols ---
    {
        const int g0 = cg * 10;
        unsigned long long acc[4][10];
#pragma unroll
        for (int q = 0; q < 4; q++)
#pragma unroll
            for (int p = 0; p < 10; p++) acc[q][p] = 0ull;

#pragma unroll 4
        for (int kp = 0; kp < J_ / 2; kp++) {
            const int k = kp * 2;
            unsigned long long fr[4], wg[10];
#pragma unroll
            for (int q = 0; q < 4; q++)
                fr[q] = *reinterpret_cast<const unsigned long long*>(&sm.x[r0 + q][k]);
#pragma unroll
            for (int p = 0; p < 10; p++)
                wg[p] = *reinterpret_cast<const unsigned long long*>(&sm.wih[g0 + p][k]);
#pragma unroll
            for (int q = 0; q < 4; q++)
#pragma unroll
                for (int p = 0; p < 10; p++) fma2(acc[q][p], fr[q], wg[p]);
        }
        const size_t rowbase = (size_t)tile * TILE_R;
#pragma unroll
        for (int q = 0; q < 4; q++) {
            float* op = g_gx + (rowbase + r0 + q) * G_ + g0;
#pragma unroll
            for (int p = 0; p < 10; p++) {
                float lo, hi;
                upk2(acc[q][p], lo, hi);
                op[p] = lo + hi + sm.b2v[g0 + p];
            }
        }
    }
}

// ---------------- LSTM recurrence: one warp per batch element ----------------
// Lane j (<20) owns h[j], c[j] and the 4 gate rows for index j (W_hh packed f32x2).
// h broadcast via shfl; gx streamed with 4-step lookahead (double-buffered chunks).

__global__ __launch_bounds__(32, 1) void lstm_kernel(
    const float* __restrict__ Whh, const float* __restrict__ Wf,
    const float* __restrict__ bf, const float* __restrict__ h0,
    const float* __restrict__ c0, float* __restrict__ out)
{
    const int b    = blockIdx.x;
    const int lane = threadIdx.x;
    const int j    = (lane < H_) ? lane : 0;  // lanes 20..31 clone lane 0 (harmless)

    unsigned long long wif[H_], wgo[H_];
#pragma unroll
    for (int k = 0; k < H_; k++) {
        wif[k] = pk2(Whh[(0 * H_ + j) * H_ + k], Whh[(1 * H_ + j) * H_ + k]);
        wgo[k] = pk2(Whh[(2 * H_ + j) * H_ + k], Whh[(3 * H_ + j) * H_ + k]);
    }

    float h = h0[b * H_ + j];
    float c = c0[b * H_ + j];
    float hsum = 0.f;

    const float* gb = g_gx + (size_t)b * G_ + j;
    const size_t stp = (size_t)B_ * G_;  // stride per timestep

    auto load4 = [&](int s0, float (&dst)[16]) {
#pragma unroll
        for (int u = 0; u < 4; u++) {
            const float* p = gb + (size_t)(s0 + u) * stp;
            dst[4 * u + 0] = p[0];
            dst[4 * u + 1] = p[20];
            dst[4 * u + 2] = p[40];
            dst[4 * u + 3] = p[60];
        }
    };

    auto step = [&](const float* g4) {
        unsigned long long aif = pk2(g4[0], g4[1]);
        unsigned long long ago = pk2(g4[2], g4[3]);
#pragma unroll
        for (int k = 0; k < H_; k++) {
            float hk = __shfl_sync(0xffffffffu, h, k);
            unsigned long long h2 = pk2(hk, hk);
            fma2(aif, wif[k], h2);
            fma2(ago, wgo[k], h2);
        }
        float ai, af, ag, ao;
        upk2(aif, ai, af);
        upk2(ago, ag, ao);
        float ig = sigmoid_f(ai);
        float fg = sigmoid_f(af);
        float gg = tanh_f(ag);
        float og = sigmoid_f(ao);
        c = fg * c + ig * gg;
        h = og * tanh_f(c);
        hsum += h;
    };

    float bufA[16], bufB[16];
    load4(0, bufA);
    for (int s0 = 0; s0 < S_; s0 += 8) {
        load4(s0 + 4, bufB);
#pragma unroll
        for (int u = 0; u < 4; u++) step(&bufA[4 * u]);
        if (s0 + 8 < S_) load4(s0 + 8, bufA);
#pragma unroll
        for (int u = 0; u < 4; u++) step(&bufB[4 * u]);
    }

    // y = Wf @ (hsum / S) + bf  (mean commutes with the linear layer)
    float w0 = (lane < H_) ? Wf[lane] : 0.f;
    float w1 = (lane < H_) ? Wf[H_ + lane] : 0.f;
    float p0 = w0 * hsum;
    float p1 = w1 * hsum;
#pragma unroll
    for (int off = 16; off; off >>= 1) {
        p0 += __shfl_xor_sync(0xffffffffu, p0, off);
        p1 += __shfl_xor_sync(0xffffffffu, p1, off);
    }
    if (lane == 0) {
        out[2 * b + 0] = p0 * (1.f / S_) + bf[0];
        out[2 * b + 1] = p1 * (1.f / S_) + bf[1];
    }
}

// ---------------- launch ----------------
extern "C" void kernel_launch(void* const* d_in, const int* in_sizes, int n_in,
                              void* d_out, int out_size)
{
    const float* feed = (const float*)d_in[0];
    const float* W1   = (const float*)d_in[1];
    const float* b1   = (const float*)d_in[2];
    const float* Wih  = (const float*)d_in[3];
    const float* Whh  = (const float*)d_in[4];
    const float* bih  = (const float*)d_in[5];
    const float* bhh  = (const float*)d_in[6];
    const float* Wf   = (const float*)d_in[7];
    const float* bf   = (const float*)d_in[8];
    const float* h0   = (const float*)d_in[9];
    const float* c0   = (const float*)d_in[10];
    float* out = (float*)d_out;

    cudaFuncSetAttribute(gemm_kernel, cudaFuncAttributeMaxDynamicSharedMemorySize,
                         (int)sizeof(SmemG));
    gemm_kernel<<<(S_ * B_) / TILE_R, 256, sizeof(SmemG)>>>(feed, W1, b1, Wih, bih, bhh);
    lstm_kernel<<<B_, 32>>>(Whh, Wf, bf, h0, c0, out);
}

// round 2
// speedup vs baseline: 1.0137x; 1.0137x over previous
#include <cuda_runtime.h>

// Problem constants
#define B_  256
#define S_  2048
#define I_  128
#define J_  40    // LSTM_IN
#define G_  80    // 4*H
#define H_  20

// Scratch: gx[s][b][g]  (S*B*80 floats = 167.8 MB) — device global, allocation-free.
__device__ float g_gx[(size_t)S_ * B_ * G_];

// ---------------- f32x2 packed helpers (sm_103a) ----------------
__device__ __forceinline__ unsigned long long pk2(float lo, float hi) {
    unsigned long long r;
    asm("mov.b64 %0, {%1, %2};" : "=l"(r) : "f"(lo), "f"(hi));
    return r;
}
__device__ __forceinline__ void upk2(unsigned long long v, float& lo, float& hi) {
    asm("mov.b64 {%0, %1}, %2;" : "=f"(lo), "=f"(hi) : "l"(v));
}
__device__ __forceinline__ void fma2(unsigned long long& d, unsigned long long a,
                                     unsigned long long b) {
    asm("fma.rn.f32x2 %0, %1, %2, %0;" : "+l"(d) : "l"(a), "l"(b));
}

__device__ __forceinline__ float sigmoid_f(float x) {
    // exp(-x) underflows/overflows gracefully (0 or inf) -> sigmoid -> 1 or 0. Safe.
    float e = __expf(-x);
    return __fdividef(1.f, 1.f + e);
}
__device__ __forceinline__ float tanh_f(float x) {
    // clamp to avoid inf/inf = NaN for very negative args
    x = fminf(fmaxf(x, -15.f), 15.f);
    float e = __expf(-2.f * x);
    return __fdividef(1.f - e, 1.f + e);
}

// ---------------- GEMM kernel: gx = relu(feed@W1^T + b1) @ Wih^T + (bih+bhh) ----------------
// Tile: 128 rows (= fixed s, 128 consecutive b) per block, 256 threads.
// Thread tile phase1: 4 rows x 5 cols (j). Phase2: 4 rows x 10 cols (g).
// k-paired f32x2 accumulation: even-k partials in .lo, odd-k in .hi.

#define TILE_R 128

struct SmemG {
    float feed[TILE_R][I_ + 4];  // stride 132 (16B-aligned rows, 2-way worst conflict)
    float x[TILE_R][J_ + 4];     // stride 44
    float w1[J_][I_ + 4];        // stride 132
    float wih[G_][J_ + 2];       // stride 42 (conflict-free for g = cg*10+p pattern)
    float b1v[J_];
    float b2v[G_];
};

__global__ __launch_bounds__(256, 1) void gemm_kernel(
    const float* __restrict__ feed, const float* __restrict__ W1,
    const float* __restrict__ b1, const float* __restrict__ Wih,
    const float* __restrict__ bih, const float* __restrict__ bhh)
{
    extern __shared__ char smem_raw[];
    SmemG& sm = *reinterpret_cast<SmemG*>(smem_raw);
    const int tid  = threadIdx.x;
    const int tile = blockIdx.x;           // 4096 tiles
    const int s    = tile >> 1;            // 2 tiles per timestep
    const int bb   = (tile & 1) * 128;     // batch base

    // --- stage weights/biases ---
    for (int idx = tid; idx < J_ * I_; idx += 256)
        sm.w1[idx / I_][idx % I_] = W1[idx];
    for (int idx = tid; idx < G_ * J_; idx += 256)
        sm.wih[idx / J_][idx % J_] = Wih[idx];
    if (tid < J_) sm.b1v[tid] = b1[tid];
    if (tid < G_) sm.b2v[tid] = bih[tid] + bhh[tid];

    // --- stage feed tile: 128 rows x 128 f32, float4, coalesced per warp ---
    for (int idx = tid; idx < TILE_R * (I_ / 4); idx += 256) {
        int r  = idx >> 5;       // row 0..127
        int c4 = idx & 31;       // float4 index 0..31
        float4 v = *reinterpret_cast<const float4*>(
            feed + ((size_t)(bb + r) * S_ + s) * I_ + c4 * 4);
        *reinterpret_cast<float4*>(&sm.feed[r][c4 * 4]) = v;
    }
    __syncthreads();

    const int cg = tid & 7;   // 8 col groups
    const int rg = tid >> 3;  // 32 row groups
    const int r0 = rg * 4;

    // --- phase 1: x[r][j], j0 = cg*5, 5 cols ---
    {
        const int j0 = cg * 5;
        unsigned long long acc[4][5];
#pragma unroll
        for (int q = 0; q < 4; q++)
#pragma unroll
            for (int p = 0; p < 5; p++) acc[q][p] = 0ull;

#pragma unroll 4
        for (int kp = 0; kp < I_ / 2; kp++) {
            const int k = kp * 2;
            unsigned long long fr[4], wj[5];
#pragma unroll
            for (int q = 0; q < 4; q++)
                fr[q] = *reinterpret_cast<const unsigned long long*>(&sm.feed[r0 + q][k]);
#pragma unroll
            for (int p = 0; p < 5; p++)
                wj[p] = *reinterpret_cast<const unsigned long long*>(&sm.w1[j0 + p][k]);
#pragma unroll
            for (int q = 0; q < 4; q++)
#pragma unroll
                for (int p = 0; p < 5; p++) fma2(acc[q][p], fr[q], wj[p]);
        }
#pragma unroll
        for (int q = 0; q < 4; q++)
#pragma unroll
            for (int p = 0; p < 5; p++) {
                float lo, hi;
                upk2(acc[q][p], lo, hi);
                float v = lo + hi + sm.b1v[j0 + p];
                sm.x[r0 + q][j0 + p] = fmaxf(v, 0.f);
            }
    }
    __syncthreads();

    // --- phase 2: gx[r][g], g0 = cg*10, 10 cols ---
    {
        const int g0 = cg * 10;
        unsigned long long acc[4][10];
#pragma unroll
        for (int q = 0; q < 4; q++)
#pragma unroll
            for (int p = 0; p < 10; p++) acc[q][p] = 0ull;

#pragma unroll 4
        for (int kp = 0; kp < J_ / 2; kp++) {
            const int k = kp * 2;
            unsigned long long fr[4], wg[10];
#pragma unroll
            for (int q = 0; q < 4; q++)
                fr[q] = *reinterpret_cast<const unsigned long long*>(&sm.x[r0 + q][k]);
#pragma unroll
            for (int p = 0; p < 10; p++)
                wg[p] = *reinterpret_cast<const unsigned long long*>(&sm.wih[g0 + p][k]);
#pragma unroll
            for (int q = 0; q < 4; q++)
#pragma unroll
                for (int p = 0; p < 10; p++) fma2(acc[q][p], fr[q], wg[p]);
        }
        const size_t rowbase = (size_t)tile * TILE_R;
#pragma unroll
        for (int q = 0; q < 4; q++) {
            float* op = g_gx + (rowbase + r0 + q) * G_ + g0;
#pragma unroll
            for (int p = 0; p < 10; p++) {
                float lo, hi;
                upk2(acc[q][p], lo, hi);
                op[p] = lo + hi + sm.b2v[g0 + p];
            }
        }
    }
}

// ---------------- LSTM recurrence: one warp per batch element ----------------
// Lane j (<20) owns h[j], c[j] and the 4 gate rows for index j (W_hh packed f32x2).
// h broadcast via shfl; gx streamed with 4-step lookahead (double-buffered chunks).

__global__ __launch_bounds__(32, 1) void lstm_kernel(
    const float* __restrict__ Whh, const float* __restrict__ Wf,
    const float* __restrict__ bf, const float* __restrict__ h0,
    const float* __restrict__ c0, float* __restrict__ out)
{
    const int b    = blockIdx.x;
    const int lane = threadIdx.x;
    const int j    = (lane < H_) ? lane : 0;  // lanes 20..31 clone lane 0 (harmless)

    unsigned long long wif[H_], wgo[H_];
#pragma unroll
    for (int k = 0; k < H_; k++) {
        wif[k] = pk2(Whh[(0 * H_ + j) * H_ + k], Whh[(1 * H_ + j) * H_ + k]);
        wgo[k] = pk2(Whh[(2 * H_ + j) * H_ + k], Whh[(3 * H_ + j) * H_ + k]);
    }

    float h = h0[b * H_ + j];
    float c = c0[b * H_ + j];
    float hsum = 0.f;

    const float* gb = g_gx + (size_t)b * G_ + j;
    const size_t stp = (size_t)B_ * G_;  // stride per timestep

    auto load4 = [&](int s0, float (&dst)[16]) {
#pragma unroll
        for (int u = 0; u < 4; u++) {
            const float* p = gb + (size_t)(s0 + u) * stp;
            dst[4 * u + 0] = p[0];
            dst[4 * u + 1] = p[20];
            dst[4 * u + 2] = p[40];
            dst[4 * u + 3] = p[60];
        }
    };

    auto step = [&](const float* g4) {
        unsigned long long aif = pk2(g4[0], g4[1]);
        unsigned long long ago = pk2(g4[2], g4[3]);
#pragma unroll
        for (int k = 0; k < H_; k++) {
            float hk = __shfl_sync(0xffffffffu, h, k);
            unsigned long long h2 = pk2(hk, hk);
            fma2(aif, wif[k], h2);
            fma2(ago, wgo[k], h2);
        }
        float ai, af, ag, ao;
        upk2(aif, ai, af);
        upk2(ago, ag, ao);
        float ig = sigmoid_f(ai);
        float fg = sigmoid_f(af);
        float gg = tanh_f(ag);
        float og = sigmoid_f(ao);
        c = fg * c + ig * gg;
        h = og * tanh_f(c);
        hsum += h;
    };

    float bufA[16], bufB[16];
    load4(0, bufA);
    for (int s0 = 0; s0 < S_; s0 += 8) {
        load4(s0 + 4, bufB);
#pragma unroll
        for (int u = 0; u < 4; u++) step(&bufA[4 * u]);
        if (s0 + 8 < S_) load4(s0 + 8, bufA);
#pragma unroll
        for (int u = 0; u < 4; u++) step(&bufB[4 * u]);
    }

    // y = Wf @ (hsum / S) + bf  (mean commutes with the linear layer)
    float w0 = (lane < H_) ? Wf[lane] : 0.f;
    float w1 = (lane < H_) ? Wf[H_ + lane] : 0.f;
    float p0 = w0 * hsum;
    float p1 = w1 * hsum;
#pragma unroll
    for (int off = 16; off; off >>= 1) {
        p0 += __shfl_xor_sync(0xffffffffu, p0, off);
        p1 += __shfl_xor_sync(0xffffffffu, p1, off);
    }
    if (lane == 0) {
        out[2 * b + 0] = p0 * (1.f / S_) + bf[0];
        out[2 * b + 1] = p1 * (1.f / S_) + bf[1];
    }
}

// ---------------- launch ----------------
extern "C" void kernel_launch(void* const* d_in, const int* in_sizes, int n_in,
                              void* d_out, int out_size)
{
    const float* feed = (const float*)d_in[0];
    const float* W1   = (const float*)d_in[1];
    const float* b1   = (const float*)d_in[2];
    const float* Wih  = (const float*)d_in[3];
    const float* Whh  = (const float*)d_in[4];
    const float* bih  = (const float*)d_in[5];
    const float* bhh  = (const float*)d_in[6];
    const float* Wf   = (const float*)d_in[7];
    const float* bf   = (const float*)d_in[8];
    const float* h0   = (const float*)d_in[9];
    const float* c0   = (const float*)d_in[10];
    float* out = (float*)d_out;

    cudaFuncSetAttribute(gemm_kernel, cudaFuncAttributeMaxDynamicSharedMemorySize,
                         (int)sizeof(SmemG));
    gemm_kernel<<<(S_ * B_) / TILE_R, 256, sizeof(SmemG)>>>(feed, W1, b1, Wih, bih, bhh);
    lstm_kernel<<<B_, 32>>>(Whh, Wf, bf, h0, c0, out);
}

// round 3
// speedup vs baseline: 1.1101x; 1.0951x over previous
#include <cuda_runtime.h>

// Problem constants
#define B_  256
#define S_  2048
#define I_  128
#define J_  40    // LSTM_IN
#define G_  80    // 4*H
#define H_  20

typedef unsigned long long u64;

// Scratch: gx, layout [b][s][80] where the 80 floats per (b,s) are permuted:
//   pos 2j   = gate i, row j      pos 2j+1 = gate f, row j   (j = 0..19)
//   pos 40+2j = gate g, row j     pos 41+2j = gate o, row j
// so LSTM lane j reads one u64 (i,f) at 2j and one u64 (g,o) at 40+2j.
__device__ __align__(256) float g_gx[(size_t)S_ * B_ * G_];

// ---------------- f32x2 packed helpers (sm_103a) ----------------
__device__ __forceinline__ u64 pk2(float lo, float hi) {
    u64 r;
    asm("mov.b64 %0, {%1, %2};" : "=l"(r) : "f"(lo), "f"(hi));
    return r;
}
__device__ __forceinline__ void upk2(u64 v, float& lo, float& hi) {
    asm("mov.b64 {%0, %1}, %2;" : "=f"(lo), "=f"(hi) : "l"(v));
}
__device__ __forceinline__ void fma2(u64& d, u64 a, u64 b) {
    asm("fma.rn.f32x2 %0, %1, %2, %0;" : "+l"(d) : "l"(a), "l"(b));
}
__device__ __forceinline__ u64 add2(u64 a, u64 b) {
    u64 r;
    asm("add.rn.f32x2 %0, %1, %2;" : "=l"(r) : "l"(a), "l"(b));
    return r;
}

__device__ __forceinline__ float sigmoid_f(float x) {
    float e = __expf(-x);
    return __fdividef(1.f, 1.f + e);
}
// tanh(x) = 1 - 2/(e^{2x}+1); branch-free, saturates correctly at +-inf.
__device__ __forceinline__ float tanh_f(float x) {
    float e2 = __expf(2.f * x);
    return 1.f - 2.f * __fdividef(1.f, e2 + 1.f);
}

// ---------------- GEMM kernel ----------------
// gx = relu(feed@W1^T + b1) @ Wih^T + (bih+bhh), written pair-permuted b-major.
// Block: 128 rows (fixed s, 128 consecutive b), 256 threads.
// Thread rows: {rg, rg+32, rg+64, rg+96} (conflict-free bank spread).

#define TILE_R 128

struct SmemG {
    float feed[TILE_R][I_ + 4];  // stride 132 words (16B-aligned rows)
    float x[TILE_R][J_ + 4];     // stride 44
    float w1[J_][I_ + 4];        // stride 132
    float wih[G_][J_ + 2];       // stride 42
    float b1v[J_];
    float b2v[G_];
};

__global__ __launch_bounds__(256, 1) void gemm_kernel(
    const float* __restrict__ feed, const float* __restrict__ W1,
    const float* __restrict__ b1, const float* __restrict__ Wih,
    const float* __restrict__ bih, const float* __restrict__ bhh)
{
    extern __shared__ char smem_raw[];
    SmemG& sm = *reinterpret_cast<SmemG*>(smem_raw);
    const int tid  = threadIdx.x;
    const int tile = blockIdx.x;           // 4096 tiles
    const int s    = tile >> 1;            // 2 tiles per timestep
    const int bb   = (tile & 1) * 128;     // batch base

    // --- stage weights/biases ---
    for (int idx = tid; idx < J_ * I_; idx += 256)
        sm.w1[idx / I_][idx % I_] = W1[idx];
    for (int idx = tid; idx < G_ * J_; idx += 256)
        sm.wih[idx / J_][idx % J_] = Wih[idx];
    if (tid < J_) sm.b1v[tid] = b1[tid];
    if (tid < G_) sm.b2v[tid] = bih[tid] + bhh[tid];

    // --- stage feed tile (float4, coalesced) ---
    for (int idx = tid; idx < TILE_R * (I_ / 4); idx += 256) {
        int r  = idx >> 5;
        int c4 = idx & 31;
        float4 v = *reinterpret_cast<const float4*>(
            feed + ((size_t)(bb + r) * S_ + s) * I_ + c4 * 4);
        *reinterpret_cast<float4*>(&sm.feed[r][c4 * 4]) = v;
    }
    __syncthreads();

    const int cg = tid & 7;   // 8 col groups
    const int rg = tid >> 3;  // 32 row groups; rows rg + 32q

    // --- phase 1: x[r][j], j0 = cg*5, LDS.128 k-quads ---
    {
        const int j0 = cg * 5;
        u64 acc[4][5];
#pragma unroll
        for (int q = 0; q < 4; q++)
#pragma unroll
            for (int p = 0; p < 5; p++) acc[q][p] = 0ull;

#pragma unroll 2
        for (int k4 = 0; k4 < I_ / 4; k4++) {
            const int k = k4 * 4;
            ulonglong2 fr[4], wj[5];
#pragma unroll
            for (int q = 0; q < 4; q++)
                fr[q] = *reinterpret_cast<const ulonglong2*>(&sm.feed[rg + 32 * q][k]);
#pragma unroll
            for (int p = 0; p < 5; p++)
                wj[p] = *reinterpret_cast<const ulonglong2*>(&sm.w1[j0 + p][k]);
#pragma unroll
            for (int q = 0; q < 4; q++)
#pragma unroll
                for (int p = 0; p < 5; p++) {
                    fma2(acc[q][p], fr[q].x, wj[p].x);
                    fma2(acc[q][p], fr[q].y, wj[p].y);
                }
        }
#pragma unroll
        for (int q = 0; q < 4; q++)
#pragma unroll
            for (int p = 0; p < 5; p++) {
                float lo, hi;
                upk2(acc[q][p], lo, hi);
                float v = lo + hi + sm.b1v[j0 + p];
                sm.x[rg + 32 * q][j0 + p] = fmaxf(v, 0.f);
            }
    }
    __syncthreads();

    // --- phase 2: gates, g0 = cg*10 ---
    {
        const int g0 = cg * 10;
        u64 acc[4][10];
#pragma unroll
        for (int q = 0; q < 4; q++)
#pragma unroll
            for (int p = 0; p < 10; p++) acc[q][p] = 0ull;

#pragma unroll 2
        for (int kp = 0; kp < J_ / 2; kp++) {
            const int k = kp * 2;
            u64 fr[4], wg[10];
#pragma unroll
            for (int q = 0; q < 4; q++)
                fr[q] = *reinterpret_cast<const u64*>(&sm.x[rg + 32 * q][k]);
#pragma unroll
            for (int p = 0; p < 10; p++)
                wg[p] = *reinterpret_cast<const u64*>(&sm.wih[g0 + p][k]);
#pragma unroll
            for (int q = 0; q < 4; q++)
#pragma unroll
                for (int p = 0; p < 10; p++) fma2(acc[q][p], fr[q], wg[p]);
        }

        // permuted positions: gate t = g/20, row j = g%20
        int pos[10];
#pragma unroll
        for (int p = 0; p < 10; p++) {
            int g = g0 + p;
            int t = g / 20;
            int jj = g - t * 20;
            pos[p] = (t < 2) ? (2 * jj + t) : (40 + 2 * jj + (t - 2));
        }
#pragma unroll
        for (int q = 0; q < 4; q++) {
            int r = rg + 32 * q;
            float* op = g_gx + ((size_t)(bb + r) * S_ + s) * G_;
#pragma unroll
            for (int p = 0; p < 10; p++) {
                float lo, hi;
                upk2(acc[q][p], lo, hi);
                op[pos[p]] = lo + hi + sm.b2v[g0 + p];
            }
        }
    }
}

// ---------------- LSTM recurrence: one warp = 2 batch elements ----------------
// Lane j (<20) owns h[j],c[j] for both batches; W_hh packed f32x2 (i,f)/(g,o).
// gx pre-packed: 2 LDG.64 per step per batch, 4-step register ring prefetch.
// Matvec: 4 split chains of 10 fma2 (half the dependent-chain latency).

__global__ __launch_bounds__(32, 1) void lstm_kernel(
    const float* __restrict__ Whh, const float* __restrict__ Wf,
    const float* __restrict__ bf, const float* __restrict__ h0,
    const float* __restrict__ c0, float* __restrict__ out)
{
    const int pr   = blockIdx.x;            // 0..127
    const int lane = threadIdx.x;
    const int j    = (lane < H_) ? lane : 0;
    const int b0   = pr * 2, b1 = b0 + 1;

    u64 wif[H_], wgo[H_];
#pragma unroll
    for (int k = 0; k < H_; k++) {
        wif[k] = pk2(Whh[(0 * H_ + j) * H_ + k], Whh[(1 * H_ + j) * H_ + k]);
        wgo[k] = pk2(Whh[(2 * H_ + j) * H_ + k], Whh[(3 * H_ + j) * H_ + k]);
    }

    float hA = h0[b0 * H_ + j], cA = c0[b0 * H_ + j], sA = 0.f;
    float hB = h0[b1 * H_ + j], cB = c0[b1 * H_ + j], sB = 0.f;

    const float* gxA = g_gx + (size_t)b0 * S_ * G_;
    const float* gxB = g_gx + (size_t)b1 * S_ * G_;
    const int oIF = 2 * j;
    const int oGO = 40 + 2 * j;

    u64 fifA[4], fgoA[4], fifB[4], fgoB[4];
#pragma unroll
    for (int u = 0; u < 4; u++) {
        fifA[u] = *reinterpret_cast<const u64*>(gxA + (size_t)u * G_ + oIF);
        fgoA[u] = *reinterpret_cast<const u64*>(gxA + (size_t)u * G_ + oGO);
        fifB[u] = *reinterpret_cast<const u64*>(gxB + (size_t)u * G_ + oIF);
        fgoB[u] = *reinterpret_cast<const u64*>(gxB + (size_t)u * G_ + oGO);
    }

    auto step = [&](u64 aif, u64 ago, float& h, float& c, float& hs) {
        u64 aif1 = 0ull, ago1 = 0ull;
#pragma unroll
        for (int k = 0; k < 10; k++) {
            float hk = __shfl_sync(0xffffffffu, h, k);
            u64 h2 = pk2(hk, hk);
            fma2(aif, wif[k], h2);
            fma2(ago, wgo[k], h2);
        }
#pragma unroll
        for (int k = 10; k < 20; k++) {
            float hk = __shfl_sync(0xffffffffu, h, k);
            u64 h2 = pk2(hk, hk);
            fma2(aif1, wif[k], h2);
            fma2(ago1, wgo[k], h2);
        }
        aif = add2(aif, aif1);
        ago = add2(ago, ago1);
        float ai, af, ag, ao;
        upk2(aif, ai, af);
        upk2(ago, ag, ao);
        float ig = sigmoid_f(ai);
        float fg = sigmoid_f(af);
        float gg = tanh_f(ag);
        float og = sigmoid_f(ao);
        c = fmaf(fg, c, ig * gg);
        h = og * tanh_f(c);
        hs += h;
    };

    for (int s = 0; s < S_; s += 4) {
#pragma unroll
        for (int u = 0; u < 4; u++) {
            step(fifA[u], fgoA[u], hA, cA, sA);
            step(fifB[u], fgoB[u], hB, cB, sB);
            int sp = s + 4 + u;
            if (sp < S_) {
                fifA[u] = *reinterpret_cast<const u64*>(gxA + (size_t)sp * G_ + oIF);
                fgoA[u] = *reinterpret_cast<const u64*>(gxA + (size_t)sp * G_ + oGO);
                fifB[u] = *reinterpret_cast<const u64*>(gxB + (size_t)sp * G_ + oIF);
                fgoB[u] = *reinterpret_cast<const u64*>(gxB + (size_t)sp * G_ + oGO);
            }
        }
    }

    // y = Wf @ (hsum / S) + bf (mean commutes with the linear layer)
    float wa = (lane < H_) ? Wf[lane] : 0.f;
    float wb = (lane < H_) ? Wf[H_ + lane] : 0.f;
    float y0A = wa * sA, y1A = wb * sA, y0B = wa * sB, y1B = wb * sB;
#pragma unroll
    for (int off = 16; off; off >>= 1) {
        y0A += __shfl_xor_sync(0xffffffffu, y0A, off);
        y1A += __shfl_xor_sync(0xffffffffu, y1A, off);
        y0B += __shfl_xor_sync(0xffffffffu, y0B, off);
        y1B += __shfl_xor_sync(0xffffffffu, y1B, off);
    }
    if (lane == 0) {
        out[2 * b0 + 0] = y0A * (1.f / S_) + bf[0];
        out[2 * b0 + 1] = y1A * (1.f / S_) + bf[1];
        out[2 * b1 + 0] = y0B * (1.f / S_) + bf[0];
        out[2 * b1 + 1] = y1B * (1.f / S_) + bf[1];
    }
}

// ---------------- launch ----------------
extern "C" void kernel_launch(void* const* d_in, const int* in_sizes, int n_in,
                              void* d_out, int out_size)
{
    const float* feed = (const float*)d_in[0];
    const float* W1   = (const float*)d_in[1];
    const float* b1   = (const float*)d_in[2];
    const float* Wih  = (const float*)d_in[3];
    const float* Whh  = (const float*)d_in[4];
    const float* bih  = (const float*)d_in[5];
    const float* bhh  = (const float*)d_in[6];
    const float* Wf   = (const float*)d_in[7];
    const float* bf   = (const float*)d_in[8];
    const float* h0   = (const float*)d_in[9];
    const float* c0   = (const float*)d_in[10];
    float* out = (float*)d_out;

    cudaFuncSetAttribute(gemm_kernel, cudaFuncAttributeMaxDynamicSharedMemorySize,
                         (int)sizeof(SmemG));
    gemm_kernel<<<(S_ * B_) / TILE_R, 256, sizeof(SmemG)>>>(feed, W1, b1, Wih, bih, bhh);
    lstm_kernel<<<B_ / 2, 32>>>(Whh, Wf, bf, h0, c0, out);
}